// round 1
// baseline (speedup 1.0000x reference)
#include <cuda_runtime.h>
#include <math.h>

#define BATCH 8
#define NPTS  4096
#define DIM   512
#define KC    512
#define OUTD  10

// ---------------- scratch (static device globals; no allocs) ----------------
__device__ float g_buf0[(size_t)BATCH * NPTS * DIM];
__device__ float g_buf1[(size_t)BATCH * NPTS * DIM];
__device__ float g_centers[(size_t)BATCH * KC * DIM];
__device__ float g_x2[BATCH * NPTS];
__device__ float g_c2[BATCH * KC];
__device__ unsigned long long g_best[BATCH * NPTS];
__device__ float g_pooled[BATCH * DIM];

__device__ __forceinline__ float mishf(float x) {
    // jax.nn.softplus = logaddexp(x, 0) = max(x,0) + log1p(exp(-|x|))
    float sp = fmaxf(x, 0.0f) + log1pf(expf(-fabsf(x)));
    return x * tanhf(sp);
}

// ---------------- row squared norms ----------------
__global__ void rowsq_kernel(const float* __restrict__ X) {
    int b = blockIdx.y, i = blockIdx.x, t = threadIdx.x;  // 128 threads
    const float* row = X + ((size_t)b * NPTS + i) * DIM;
    float s = 0.f;
#pragma unroll
    for (int u = 0; u < 4; u++) { float v = row[t + 128 * u]; s += v * v; }
    for (int o = 16; o > 0; o >>= 1) s += __shfl_down_sync(0xffffffffu, s, o);
    __shared__ float w[4];
    if ((t & 31) == 0) w[t >> 5] = s;
    __syncthreads();
    if (t == 0) g_x2[b * NPTS + i] = w[0] + w[1] + w[2] + w[3];
}

// ---------------- centers0 = X[:KC]; c2 = rowsq(centers) ----------------
__global__ void init_centers_kernel(const float* __restrict__ X) {
    int b = blockIdx.y, k = blockIdx.x, t = threadIdx.x;  // 128 threads
    const float* row = X + ((size_t)b * NPTS + k) * DIM;
    float* crow = g_centers + ((size_t)b * KC + k) * DIM;
    float s = 0.f;
#pragma unroll
    for (int u = 0; u < 4; u++) {
        float v = row[t + 128 * u];
        crow[t + 128 * u] = v;
        s += v * v;
    }
    for (int o = 16; o > 0; o >>= 1) s += __shfl_down_sync(0xffffffffu, s, o);
    __shared__ float w[4];
    if ((t & 31) == 0) w[t >> 5] = s;
    __syncthreads();
    if (t == 0) g_c2[b * KC + k] = w[0] + w[1] + w[2] + w[3];
}

__global__ void reset_best_kernel() {
    int i = blockIdx.x * blockDim.x + threadIdx.x;
    if (i < BATCH * NPTS) g_best[i] = 0xFFFFFFFFFFFFFFFFull;
}

// ---------------- assignment: argmin_k (x2 + c2 - 2 X.C^T) ----------------
// 64x64 tile, BK=16, 256 threads, 4x4 micro-tile. Exact JAX tie semantics via
// (ordered-float(dist) << 32 | k) atomicMin (min value, then lowest index).
__global__ __launch_bounds__(256) void assign_kernel(const float* __restrict__ X) {
    int b = blockIdx.z;
    const float* A = X + (size_t)b * NPTS * DIM;
    const float* C = g_centers + (size_t)b * KC * DIM;
    int m0 = blockIdx.x * 64, n0 = blockIdx.y * 64;

    __shared__ float As[16][64];
    __shared__ float Bs[16][64];
    __shared__ unsigned long long skey[64];

    int tid = threadIdx.x;
    int tx = tid & 15, ty = tid >> 4;
    int lr = tid >> 2, lc = (tid & 3) * 4;

    float acc[4][4] = {};

    for (int d0 = 0; d0 < DIM; d0 += 16) {
        float4 av = *(const float4*)(A + (size_t)(m0 + lr) * DIM + d0 + lc);
        float4 bv = *(const float4*)(C + (size_t)(n0 + lr) * DIM + d0 + lc);
        __syncthreads();
        As[lc + 0][lr] = av.x; As[lc + 1][lr] = av.y; As[lc + 2][lr] = av.z; As[lc + 3][lr] = av.w;
        Bs[lc + 0][lr] = bv.x; Bs[lc + 1][lr] = bv.y; Bs[lc + 2][lr] = bv.z; Bs[lc + 3][lr] = bv.w;
        __syncthreads();
#pragma unroll
        for (int kk = 0; kk < 16; kk++) {
            float4 a = *(const float4*)&As[kk][ty * 4];
            float4 bb = *(const float4*)&Bs[kk][tx * 4];
            float aa[4] = {a.x, a.y, a.z, a.w};
            float bbv[4] = {bb.x, bb.y, bb.z, bb.w};
#pragma unroll
            for (int i = 0; i < 4; i++)
#pragma unroll
                for (int j = 0; j < 4; j++) acc[i][j] += aa[i] * bbv[j];
        }
    }

    if (tid < 64) skey[tid] = 0xFFFFFFFFFFFFFFFFull;
    __syncthreads();

    float c2v[4], x2v[4];
#pragma unroll
    for (int j = 0; j < 4; j++) c2v[j] = g_c2[b * KC + n0 + tx * 4 + j];
#pragma unroll
    for (int i = 0; i < 4; i++) x2v[i] = g_x2[b * NPTS + m0 + ty * 4 + i];

#pragma unroll
    for (int i = 0; i < 4; i++) {
        unsigned long long best = 0xFFFFFFFFFFFFFFFFull;
#pragma unroll
        for (int j = 0; j < 4; j++) {
            float d = (x2v[i] + c2v[j]) - 2.0f * acc[i][j];
            unsigned u = __float_as_uint(d);
            u = (u & 0x80000000u) ? ~u : (u | 0x80000000u);
            unsigned long long key =
                ((unsigned long long)u << 32) | (unsigned)(n0 + tx * 4 + j);
            best = (key < best) ? key : best;
        }
        atomicMin(&skey[ty * 4 + i], best);
    }
    __syncthreads();
    if (tid < 64) atomicMin(&g_best[b * NPTS + m0 + tid], skey[tid]);
}

// ---------------- center update (deterministic ordered scan) ----------------
__global__ void update_kernel(const float* __restrict__ X) {
    int b = blockIdx.y, k = blockIdx.x, t = threadIdx.x;  // 128 threads
    __shared__ int slab[NPTS];
    const unsigned long long* best = g_best + b * NPTS;
    for (int i = t; i < NPTS; i += 128) slab[i] = (int)(best[i] & 0xFFFFFFFFu);
    __syncthreads();

    float a0 = 0, a1 = 0, a2 = 0, a3 = 0;
    int cnt = 0;
    const float* Xb = X + (size_t)b * NPTS * DIM;
    for (int i = 0; i < NPTS; i++) {
        if (slab[i] == k) {
            cnt++;
            const float* xr = Xb + (size_t)i * DIM;
            a0 += xr[t]; a1 += xr[t + 128]; a2 += xr[t + 256]; a3 += xr[t + 384];
        }
    }
    float* crow = g_centers + ((size_t)b * KC + k) * DIM;
    float v0, v1, v2, v3;
    if (cnt > 0) {
        float cf = (float)cnt;
        v0 = a0 / cf; v1 = a1 / cf; v2 = a2 / cf; v3 = a3 / cf;
        crow[t] = v0; crow[t + 128] = v1; crow[t + 256] = v2; crow[t + 384] = v3;
    } else {
        v0 = crow[t]; v1 = crow[t + 128]; v2 = crow[t + 256]; v3 = crow[t + 384];
    }
    float sq = v0 * v0 + v1 * v1 + v2 * v2 + v3 * v3;
    for (int o = 16; o > 0; o >>= 1) sq += __shfl_down_sync(0xffffffffu, sq, o);
    __shared__ float w[4];
    if ((t & 31) == 0) w[t >> 5] = sq;
    __syncthreads();
    if (t == 0) g_c2[b * KC + k] = w[0] + w[1] + w[2] + w[3];
}

// ---------------- h_next = mish(adj @ one_hot(labels)) : per-row segment sum --
__global__ __launch_bounds__(256) void segsum_mish_kernel(const float* __restrict__ adj,
                                                          float* __restrict__ Hout) {
    int b = blockIdx.y, i = blockIdx.x, t = threadIdx.x;  // 256 threads
    __shared__ float acc[KC];
    __shared__ int slab[NPTS];
    const unsigned long long* best = g_best + b * NPTS;
    for (int j = t; j < KC; j += 256) acc[j] = 0.f;
    for (int j = t; j < NPTS; j += 256) slab[j] = (int)(best[j] & 0xFFFFFFFFu);
    __syncthreads();
    const float* arow = adj + ((size_t)b * NPTS + i) * NPTS;
    for (int j = t; j < NPTS; j += 256) atomicAdd(&acc[slab[j]], arow[j]);
    __syncthreads();
    float* hrow = Hout + ((size_t)b * NPTS + i) * DIM;
    for (int k = t; k < KC; k += 256) hrow[k] = mishf(acc[k]);
}

__global__ void zero_pooled_kernel() {
    g_pooled[blockIdx.x * DIM + threadIdx.x] = 0.f;
}

// ---------------- generic NN GEMM; EPI=0 plain write, EPI=1 bias+mish+pool ----
template <int EPI>
__global__ __launch_bounds__(256) void gemm_nn_kernel(
    const float* __restrict__ A, const float* __restrict__ Bm,
    float* __restrict__ Cout, const float* __restrict__ bias,
    int M, int Kd, int Nn, size_t aStride, size_t bStride, size_t cStride) {
    int b = blockIdx.z;
    const float* Ab = A + (size_t)b * aStride;
    const float* Bb = Bm + (size_t)b * bStride;
    int m0 = blockIdx.x * 64, n0 = blockIdx.y * 64;

    __shared__ float As[16][64];
    __shared__ float Bs[16][64];

    int tid = threadIdx.x;
    int tx = tid & 15, ty = tid >> 4;
    int lr = tid >> 2, lc = (tid & 3) * 4;
    int brow = tid >> 4, bc = (tid & 15) * 4;

    float acc[4][4] = {};

    for (int d0 = 0; d0 < Kd; d0 += 16) {
        float4 av = *(const float4*)(Ab + (size_t)(m0 + lr) * Kd + d0 + lc);
        float4 bv = *(const float4*)(Bb + (size_t)(d0 + brow) * Nn + n0 + bc);
        __syncthreads();
        As[lc + 0][lr] = av.x; As[lc + 1][lr] = av.y; As[lc + 2][lr] = av.z; As[lc + 3][lr] = av.w;
        *(float4*)&Bs[brow][bc] = bv;
        __syncthreads();
#pragma unroll
        for (int kk = 0; kk < 16; kk++) {
            float4 a = *(const float4*)&As[kk][ty * 4];
            float4 bb = *(const float4*)&Bs[kk][tx * 4];
            float aa[4] = {a.x, a.y, a.z, a.w};
            float bbv[4] = {bb.x, bb.y, bb.z, bb.w};
#pragma unroll
            for (int i = 0; i < 4; i++)
#pragma unroll
                for (int j = 0; j < 4; j++) acc[i][j] += aa[i] * bbv[j];
        }
    }

    if (EPI == 0) {
#pragma unroll
        for (int i = 0; i < 4; i++) {
            float4 v = make_float4(acc[i][0], acc[i][1], acc[i][2], acc[i][3]);
            *(float4*)(Cout + (size_t)b * cStride + (size_t)(m0 + ty * 4 + i) * Nn +
                       n0 + tx * 4) = v;
        }
    } else {
        __shared__ float colsum[64];
        if (tid < 64) colsum[tid] = 0.f;
        float bj[4];
#pragma unroll
        for (int j = 0; j < 4; j++) bj[j] = bias[n0 + tx * 4 + j];
        __syncthreads();
        float part[4] = {0.f, 0.f, 0.f, 0.f};
#pragma unroll
        for (int i = 0; i < 4; i++)
#pragma unroll
            for (int j = 0; j < 4; j++) part[j] += mishf(acc[i][j] + bj[j]);
#pragma unroll
        for (int j = 0; j < 4; j++) atomicAdd(&colsum[tx * 4 + j], part[j]);
        __syncthreads();
        if (tid < 64) atomicAdd(&g_pooled[b * DIM + n0 + tid], colsum[tid]);
    }
}

// ---------------- out = pooled @ Wp + bp ----------------
__global__ void out_kernel(const float* __restrict__ Wp, const float* __restrict__ bp,
                           float* __restrict__ out) {
    int b = blockIdx.x, t = threadIdx.x;  // 32 threads
    if (t < OUTD) {
        const float* p = g_pooled + b * DIM;
        float s = 0.f;
        for (int h = 0; h < DIM; h++) s += p[h] * Wp[h * OUTD + t];
        out[b * OUTD + t] = s + bp[t];
    }
}

// ---------------- host orchestration ----------------
static void run_ctod(const float* X) {
    rowsq_kernel<<<dim3(NPTS, BATCH), 128>>>(X);
    init_centers_kernel<<<dim3(KC, BATCH), 128>>>(X);
    for (int it = 0; it < 10; it++) {
        reset_best_kernel<<<(BATCH * NPTS) / 256, 256>>>();
        assign_kernel<<<dim3(NPTS / 64, KC / 64, BATCH), 256>>>(X);
        if (it < 9) update_kernel<<<dim3(KC, BATCH), 128>>>(X);
    }
}

extern "C" void kernel_launch(void* const* d_in, const int* in_sizes, int n_in,
                              void* d_out, int out_size) {
    const float* x   = (const float*)d_in[0];
    const float* adj = (const float*)d_in[1];
    const float* W   = (const float*)d_in[2];
    const float* bb  = (const float*)d_in[3];
    const float* Wp  = (const float*)d_in[4];
    const float* bp  = (const float*)d_in[5];
    float* out = (float*)d_out;

    float *h0, *h1;
    cudaGetSymbolAddress((void**)&h0, g_buf0);
    cudaGetSymbolAddress((void**)&h1, g_buf1);

    // Layer 1: ctod(x) -> segsum -> h0
    run_ctod(x);
    segsum_mish_kernel<<<dim3(NPTS, BATCH), 256>>>(adj, h0);
    // Layer 2: ctod(h0) -> segsum -> h1
    run_ctod(h0);
    segsum_mish_kernel<<<dim3(NPTS, BATCH), 256>>>(adj, h1);
    // Layer 3: ctod(h1) -> segsum -> h0
    run_ctod(h1);
    segsum_mish_kernel<<<dim3(NPTS, BATCH), 256>>>(adj, h0);

    // Final layer: t = h0 @ W (-> h1), then mish(adj @ t + b) pooled over rows
    gemm_nn_kernel<0><<<dim3(NPTS / 64, DIM / 64, BATCH), 256>>>(
        h0, W, h1, nullptr, NPTS, DIM, DIM,
        (size_t)NPTS * DIM, (size_t)0, (size_t)NPTS * DIM);
    zero_pooled_kernel<<<BATCH, DIM>>>();
    gemm_nn_kernel<1><<<dim3(NPTS / 64, DIM / 64, BATCH), 256>>>(
        adj, h1, nullptr, bb, NPTS, NPTS, DIM,
        (size_t)NPTS * NPTS, (size_t)NPTS * DIM, (size_t)0);
    out_kernel<<<BATCH, 32>>>(Wp, bp, out);
}

// round 2
// speedup vs baseline: 1.9578x; 1.9578x over previous
#include <cuda_runtime.h>
#include <math.h>

#define BATCH 8
#define NPTS  4096
#define DIM   512
#define KC    512
#define OUTD  10

// ---------------- scratch (static device globals; no allocs) ----------------
__device__ float g_buf0[(size_t)BATCH * NPTS * DIM];
__device__ float g_buf1[(size_t)BATCH * NPTS * DIM];
__device__ float g_centers[(size_t)BATCH * KC * DIM];
__device__ float g_x2[BATCH * NPTS];
__device__ float g_c2[BATCH * KC];
__device__ unsigned long long g_best[BATCH * NPTS];
__device__ int g_labels[BATCH * NPTS];
__device__ int g_list[BATCH * NPTS];
__device__ int g_counts[BATCH * KC];
__device__ int g_offs[BATCH * KC];
__device__ float g_pooled[BATCH * DIM];

__device__ __forceinline__ float mishf(float x) {
    float sp = fmaxf(x, 0.0f) + log1pf(expf(-fabsf(x)));
    return x * tanhf(sp);
}

__device__ __forceinline__ void ffma2(unsigned long long& d, unsigned long long a,
                                      unsigned long long b) {
    asm("fma.rn.f32x2 %0, %1, %2, %0;" : "+l"(d) : "l"(a), "l"(b));
}

// ---------------- row squared norms ----------------
__global__ void rowsq_kernel(const float* __restrict__ X) {
    int b = blockIdx.y, i = blockIdx.x, t = threadIdx.x;  // 128 threads
    const float* row = X + ((size_t)b * NPTS + i) * DIM;
    float s = 0.f;
#pragma unroll
    for (int u = 0; u < 4; u++) { float v = row[t + 128 * u]; s += v * v; }
    for (int o = 16; o > 0; o >>= 1) s += __shfl_down_sync(0xffffffffu, s, o);
    __shared__ float w[4];
    if ((t & 31) == 0) w[t >> 5] = s;
    __syncthreads();
    if (t == 0) g_x2[b * NPTS + i] = w[0] + w[1] + w[2] + w[3];
}

// ---------------- centers0 = X[:KC]; c2 = rowsq(centers) ----------------
__global__ void init_centers_kernel(const float* __restrict__ X) {
    int b = blockIdx.y, k = blockIdx.x, t = threadIdx.x;  // 128 threads
    const float* row = X + ((size_t)b * NPTS + k) * DIM;
    float* crow = g_centers + ((size_t)b * KC + k) * DIM;
    float s = 0.f;
#pragma unroll
    for (int u = 0; u < 4; u++) {
        float v = row[t + 128 * u];
        crow[t + 128 * u] = v;
        s += v * v;
    }
    for (int o = 16; o > 0; o >>= 1) s += __shfl_down_sync(0xffffffffu, s, o);
    __shared__ float w[4];
    if ((t & 31) == 0) w[t >> 5] = s;
    __syncthreads();
    if (t == 0) g_c2[b * KC + k] = w[0] + w[1] + w[2] + w[3];
}

__global__ void reset_best_kernel() {
    int i = blockIdx.x * blockDim.x + threadIdx.x;
    if (i < BATCH * NPTS) g_best[i] = 0xFFFFFFFFFFFFFFFFull;
}

// ============================================================================
// Packed f32x2 GEMM core: 128x128 tile, BK=16, 256 threads, 8x8 micro-tile,
// double-buffered smem. A stored duplicated so LDS.128 yields broadcast pairs.
// MODE 0: assign (B = centers, K-inner; epilogue = keyed argmin)
// MODE 1: C = A@B (B is KxN) plain store
// MODE 2: pooled mish epilogue (bias + mish + column sum into g_pooled)
// ============================================================================
template <int MODE>
__global__ __launch_bounds__(256, 2) void gemm_kernel(
    const float* __restrict__ A, const float* __restrict__ B,
    float* __restrict__ C, const float* __restrict__ bias,
    int Kd, size_t aBatch, size_t bBatch, size_t cBatch) {
    // 48KB static smem, carved manually so the epilogue can alias it.
    __shared__ __align__(16) char smem_raw[49152];
    float(*AsD)[16][256] = (float(*)[16][256])smem_raw;            // 32KB
    float(*Bs)[16][128]  = (float(*)[16][128])(smem_raw + 32768);  // 16KB

    int b = blockIdx.z;
    const float* Ab = A + (size_t)b * aBatch;
    const float* Bb = B + (size_t)b * bBatch;
    int m0 = blockIdx.x * 128, n0 = blockIdx.y * 128;
    int tid = threadIdx.x;
    int tx = tid & 15, ty = tid >> 4;

    int am = tid >> 2, aq = tid & 3;   // A/B(transposed) vector mapping
    int bkr = tid >> 5, bnc = tid & 31;  // B (KxN) vector mapping

    float4 ra0, ra1, rb0, rb1;

    auto loadT = [&](int k0) {
        ra0 = *(const float4*)(Ab + (size_t)(m0 + am) * Kd + k0 + aq * 4);
        ra1 = *(const float4*)(Ab + (size_t)(m0 + am + 64) * Kd + k0 + aq * 4);
        if (MODE == 0) {
            rb0 = *(const float4*)(Bb + (size_t)(n0 + am) * Kd + k0 + aq * 4);
            rb1 = *(const float4*)(Bb + (size_t)(n0 + am + 64) * Kd + k0 + aq * 4);
        } else {
            rb0 = *(const float4*)(Bb + (size_t)(k0 + bkr) * 512 + n0 + bnc * 4);
            rb1 = *(const float4*)(Bb + (size_t)(k0 + bkr + 8) * 512 + n0 + bnc * 4);
        }
    };
    auto storeT = [&](int s) {
#pragma unroll
        for (int j = 0; j < 4; j++) {
            float v0 = (&ra0.x)[j], v1 = (&ra1.x)[j];
            *(float2*)&AsD[s][aq * 4 + j][2 * am] = make_float2(v0, v0);
            *(float2*)&AsD[s][aq * 4 + j][2 * (am + 64)] = make_float2(v1, v1);
        }
        if (MODE == 0) {
#pragma unroll
            for (int j = 0; j < 4; j++) {
                Bs[s][aq * 4 + j][am] = (&rb0.x)[j];
                Bs[s][aq * 4 + j][am + 64] = (&rb1.x)[j];
            }
        } else {
            *(float4*)&Bs[s][bkr][bnc * 4] = rb0;
            *(float4*)&Bs[s][bkr + 8][bnc * 4] = rb1;
        }
    };

    unsigned long long acc[8][4];
#pragma unroll
    for (int i = 0; i < 8; i++)
#pragma unroll
        for (int jp = 0; jp < 4; jp++) acc[i][jp] = 0ull;

    loadT(0);
    storeT(0);
    __syncthreads();

    int nk = Kd >> 4;
    int s = 0;
    for (int t = 0; t < nk; t++) {
        if (t + 1 < nk) loadT((t + 1) << 4);
#pragma unroll
        for (int kk = 0; kk < 16; kk++) {
            const ulonglong2* ap = (const ulonglong2*)&AsD[s][kk][ty * 16];
            const ulonglong2* bp = (const ulonglong2*)&Bs[s][kk][tx * 8];
            ulonglong2 A0 = ap[0], A1 = ap[1], A2 = ap[2], A3 = ap[3];
            ulonglong2 B0 = bp[0], B1 = bp[1];
            unsigned long long av[8] = {A0.x, A0.y, A1.x, A1.y, A2.x, A2.y, A3.x, A3.y};
            unsigned long long bv[4] = {B0.x, B0.y, B1.x, B1.y};
#pragma unroll
            for (int i = 0; i < 8; i++)
#pragma unroll
                for (int jp = 0; jp < 4; jp++) ffma2(acc[i][jp], av[i], bv[jp]);
        }
        if (t + 1 < nk) {
            storeT(s ^ 1);
            __syncthreads();
            s ^= 1;
        }
    }
    __syncthreads();  // smem is dead; epilogues may alias it

    if (MODE == 0) {
        unsigned long long* skey = (unsigned long long*)smem_raw;
        if (tid < 128) skey[tid] = 0xFFFFFFFFFFFFFFFFull;
        float c2v[8], x2v[8];
#pragma unroll
        for (int j = 0; j < 8; j++) c2v[j] = g_c2[b * KC + n0 + tx * 8 + j];
#pragma unroll
        for (int i = 0; i < 8; i++) x2v[i] = g_x2[b * NPTS + m0 + ty * 8 + i];
        __syncthreads();
#pragma unroll
        for (int i = 0; i < 8; i++) {
            unsigned long long best = 0xFFFFFFFFFFFFFFFFull;
#pragma unroll
            for (int jp = 0; jp < 4; jp++) {
                float2 dd = *(float2*)&acc[i][jp];
#pragma unroll
                for (int h = 0; h < 2; h++) {
                    float dot = (h == 0) ? dd.x : dd.y;
                    int col = n0 + tx * 8 + jp * 2 + h;
                    float d = (x2v[i] + c2v[jp * 2 + h]) - 2.0f * dot;
                    unsigned u = __float_as_uint(d);
                    u = (u & 0x80000000u) ? ~u : (u | 0x80000000u);
                    unsigned long long key =
                        ((unsigned long long)u << 32) | (unsigned)col;
                    best = (key < best) ? key : best;
                }
            }
            atomicMin(&skey[ty * 8 + i], best);
        }
        __syncthreads();
        if (tid < 128) atomicMin(&g_best[b * NPTS + m0 + tid], skey[tid]);
    } else if (MODE == 1) {
        float* Cb = C + (size_t)b * cBatch;
#pragma unroll
        for (int i = 0; i < 8; i++) {
            float2 d0 = *(float2*)&acc[i][0], d1 = *(float2*)&acc[i][1];
            float2 d2 = *(float2*)&acc[i][2], d3 = *(float2*)&acc[i][3];
            float* p = Cb + (size_t)(m0 + ty * 8 + i) * 512 + n0 + tx * 8;
            *(float4*)p = make_float4(d0.x, d0.y, d1.x, d1.y);
            *(float4*)(p + 4) = make_float4(d2.x, d2.y, d3.x, d3.y);
        }
    } else {
        float* colsum = (float*)smem_raw;
        if (tid < 128) colsum[tid] = 0.f;
        float bj[8];
#pragma unroll
        for (int j = 0; j < 8; j++) bj[j] = bias[n0 + tx * 8 + j];
        __syncthreads();
        float part[8] = {0, 0, 0, 0, 0, 0, 0, 0};
#pragma unroll
        for (int i = 0; i < 8; i++)
#pragma unroll
            for (int jp = 0; jp < 4; jp++) {
                float2 dd = *(float2*)&acc[i][jp];
                part[jp * 2 + 0] += mishf(dd.x + bj[jp * 2 + 0]);
                part[jp * 2 + 1] += mishf(dd.y + bj[jp * 2 + 1]);
            }
#pragma unroll
        for (int j = 0; j < 8; j++) atomicAdd(&colsum[tx * 8 + j], part[j]);
        __syncthreads();
        if (tid < 128) atomicAdd(&g_pooled[b * DIM + n0 + tid], colsum[tid]);
    }
}

// ---------------- deterministic cluster member-list build ----------------
// Per batch: histogram -> exclusive scan -> stable (ascending-i) rank scatter.
__global__ __launch_bounds__(256) void listbuild_kernel() {
    __shared__ int cnts[KC];
    __shared__ int offs[KC];
    __shared__ int cur[KC];
    __shared__ int labs[NPTS];
    int b = blockIdx.x, t = threadIdx.x;
    for (int k = t; k < KC; k += 256) cnts[k] = 0;
    __syncthreads();
    for (int i = t; i < NPTS; i += 256) {
        int l = (int)(g_best[b * NPTS + i] & 0xFFFFFFFFu);
        labs[i] = l;
        g_labels[b * NPTS + i] = l;
        atomicAdd(&cnts[l], 1);
    }
    __syncthreads();
    if (t < 32) {
        int carry = 0;
        for (int c = 0; c < KC / 32; c++) {
            int v = cnts[c * 32 + t];
            int x = v;
#pragma unroll
            for (int o = 1; o < 32; o <<= 1) {
                int y = __shfl_up_sync(0xffffffffu, x, o);
                if (t >= o) x += y;
            }
            offs[c * 32 + t] = carry + x - v;
            carry += __shfl_sync(0xffffffffu, x, 31);
        }
    }
    __syncthreads();
    for (int k = t; k < KC; k += 256) {
        cur[k] = offs[k];
        g_counts[b * KC + k] = cnts[k];
        g_offs[b * KC + k] = offs[k];
    }
    __syncthreads();
    if (t < 32) {
        unsigned below = (t == 0) ? 0u : (0xffffffffu >> (32 - t));
        for (int c = 0; c < NPTS / 32; c++) {
            int i = c * 32 + t;
            int l = labs[i];
            unsigned mask = __match_any_sync(0xffffffffu, l);
            int base = cur[l];
            __syncwarp();
            int rank = __popc(mask & below);
            g_list[b * NPTS + base + rank] = i;
            if (t == __ffs(mask) - 1) cur[l] = base + __popc(mask);
            __syncwarp();
        }
    }
}

// ---------------- center update: gather listed members (ascending order) ----
__global__ void gather_update_kernel(const float* __restrict__ X) {
    int b = blockIdx.y, k = blockIdx.x, t = threadIdx.x;  // 128 threads
    int cnt = g_counts[b * KC + k];
    int off = g_offs[b * KC + k];
    const int* lst = g_list + b * NPTS + off;
    const float* Xb = X + (size_t)b * NPTS * DIM;
    float a0 = 0, a1 = 0, a2 = 0, a3 = 0;
    for (int e = 0; e < cnt; e++) {
        const float* xr = Xb + (size_t)lst[e] * DIM;
        a0 += xr[t]; a1 += xr[t + 128]; a2 += xr[t + 256]; a3 += xr[t + 384];
    }
    float* crow = g_centers + ((size_t)b * KC + k) * DIM;
    float v0, v1, v2, v3;
    if (cnt > 0) {
        float cf = (float)cnt;
        v0 = a0 / cf; v1 = a1 / cf; v2 = a2 / cf; v3 = a3 / cf;
        crow[t] = v0; crow[t + 128] = v1; crow[t + 256] = v2; crow[t + 384] = v3;
    } else {
        v0 = crow[t]; v1 = crow[t + 128]; v2 = crow[t + 256]; v3 = crow[t + 384];
    }
    float sq = v0 * v0 + v1 * v1 + v2 * v2 + v3 * v3;
    for (int o = 16; o > 0; o >>= 1) sq += __shfl_down_sync(0xffffffffu, sq, o);
    __shared__ float w[4];
    if ((t & 31) == 0) w[t >> 5] = sq;
    __syncthreads();
    if (t == 0) g_c2[b * KC + k] = w[0] + w[1] + w[2] + w[3];
}

// ---------------- h_next = mish(adj @ one_hot(labels)), 8 rows/block --------
__global__ __launch_bounds__(256) void segsum_mish_kernel(const float* __restrict__ adj,
                                                          float* __restrict__ Hout) {
    int b = blockIdx.y, i0 = blockIdx.x * 8, t = threadIdx.x;  // 256 threads
    __shared__ float acc[8][KC];
    __shared__ int labs[NPTS];
    const int* lb = g_labels + b * NPTS;
    for (int j = t; j < NPTS; j += 256) labs[j] = lb[j];
#pragma unroll
    for (int r = 0; r < 8; r++)
        for (int k = t; k < KC; k += 256) acc[r][k] = 0.f;
    __syncthreads();
#pragma unroll
    for (int r = 0; r < 8; r++) {
        const float* arow = adj + ((size_t)b * NPTS + i0 + r) * NPTS;
        for (int j = t; j < NPTS; j += 256) atomicAdd(&acc[r][labs[j]], arow[j]);
    }
    __syncthreads();
#pragma unroll
    for (int r = 0; r < 8; r++) {
        float* hrow = Hout + ((size_t)b * NPTS + i0 + r) * DIM;
        for (int k = t; k < KC; k += 256) hrow[k] = mishf(acc[r][k]);
    }
}

__global__ void zero_pooled_kernel() {
    g_pooled[blockIdx.x * DIM + threadIdx.x] = 0.f;
}

// ---------------- out = pooled @ Wp + bp ----------------
__global__ void out_kernel(const float* __restrict__ Wp, const float* __restrict__ bp,
                           float* __restrict__ out) {
    int b = blockIdx.x, t = threadIdx.x;  // 32 threads
    if (t < OUTD) {
        const float* p = g_pooled + b * DIM;
        float s = 0.f;
        for (int h = 0; h < DIM; h++) s += p[h] * Wp[h * OUTD + t];
        out[b * OUTD + t] = s + bp[t];
    }
}

// ---------------- host orchestration ----------------
static void run_ctod(const float* X, const float* centers) {
    rowsq_kernel<<<dim3(NPTS, BATCH), 128>>>(X);
    init_centers_kernel<<<dim3(KC, BATCH), 128>>>(X);
    for (int it = 0; it < 10; it++) {
        reset_best_kernel<<<(BATCH * NPTS) / 256, 256>>>();
        gemm_kernel<0><<<dim3(NPTS / 128, KC / 128, BATCH), 256>>>(
            X, centers, nullptr, nullptr, DIM,
            (size_t)NPTS * DIM, (size_t)KC * DIM, (size_t)0);
        listbuild_kernel<<<BATCH, 256>>>();
        if (it < 9) gather_update_kernel<<<dim3(KC, BATCH), 128>>>(X);
    }
}

extern "C" void kernel_launch(void* const* d_in, const int* in_sizes, int n_in,
                              void* d_out, int out_size) {
    const float* x   = (const float*)d_in[0];
    const float* adj = (const float*)d_in[1];
    const float* W   = (const float*)d_in[2];
    const float* bb  = (const float*)d_in[3];
    const float* Wp  = (const float*)d_in[4];
    const float* bp  = (const float*)d_in[5];
    float* out = (float*)d_out;

    float *h0, *h1, *centers;
    cudaGetSymbolAddress((void**)&h0, g_buf0);
    cudaGetSymbolAddress((void**)&h1, g_buf1);
    cudaGetSymbolAddress((void**)&centers, g_centers);

    // Layer 1
    run_ctod(x, centers);
    segsum_mish_kernel<<<dim3(NPTS / 8, BATCH), 256>>>(adj, h0);
    // Layer 2
    run_ctod(h0, centers);
    segsum_mish_kernel<<<dim3(NPTS / 8, BATCH), 256>>>(adj, h1);
    // Layer 3
    run_ctod(h1, centers);
    segsum_mish_kernel<<<dim3(NPTS / 8, BATCH), 256>>>(adj, h0);

    // Final layer: t = h0 @ W, then pooled mish(adj @ t + b)
    gemm_kernel<1><<<dim3(NPTS / 128, DIM / 128, BATCH), 256>>>(
        h0, W, h1, nullptr, DIM,
        (size_t)NPTS * DIM, (size_t)0, (size_t)NPTS * DIM);
    zero_pooled_kernel<<<BATCH, DIM>>>();
    gemm_kernel<2><<<dim3(NPTS / 128, DIM / 128, BATCH), 256>>>(
        adj, h1, nullptr, bb, NPTS,
        (size_t)NPTS * NPTS, (size_t)NPTS * DIM, (size_t)0);
    out_kernel<<<BATCH, 32>>>(Wp, bp, out);
}

// round 5
// speedup vs baseline: 2.9413x; 1.5024x over previous
#include <cuda_runtime.h>
#include <math.h>

#define BATCH 8
#define NPTS  4096
#define DIM   512
#define KC    512
#define OUTD  10

// ---------------- scratch (static device globals; no allocs) ----------------
__device__ float g_buf0[(size_t)BATCH * NPTS * DIM];
__device__ float g_buf1[(size_t)BATCH * NPTS * DIM];
__device__ float g_centers[(size_t)BATCH * KC * DIM];
__device__ float g_x2[BATCH * NPTS];
__device__ float g_c2[BATCH * KC];
__device__ unsigned long long g_best[BATCH * NPTS];
__device__ int g_labels[BATCH * NPTS];
__device__ int g_list[BATCH * NPTS];
__device__ int g_counts[BATCH * KC];
__device__ int g_offs[BATCH * KC];
__device__ float g_pooled[BATCH * DIM];

__device__ __forceinline__ float mishf(float x) {
    float sp = fmaxf(x, 0.0f) + log1pf(expf(-fabsf(x)));
    return x * tanhf(sp);
}

__device__ __forceinline__ void ffma2(unsigned long long& d, unsigned long long a,
                                      unsigned long long b) {
    asm("fma.rn.f32x2 %0, %1, %2, %0;" : "+l"(d) : "l"(a), "l"(b));
}
__device__ __forceinline__ unsigned long long dup2(unsigned x) {
    unsigned long long r;
    asm("mov.b64 %0, {%1, %1};" : "=l"(r) : "r"(x));
    return r;
}

// ---------------- row squared norms ----------------
__global__ void rowsq_kernel(const float* __restrict__ X) {
    int b = blockIdx.y, i = blockIdx.x, t = threadIdx.x;  // 128 threads
    const float* row = X + ((size_t)b * NPTS + i) * DIM;
    float s = 0.f;
#pragma unroll
    for (int u = 0; u < 4; u++) { float v = row[t + 128 * u]; s += v * v; }
    for (int o = 16; o > 0; o >>= 1) s += __shfl_down_sync(0xffffffffu, s, o);
    __shared__ float w[4];
    if ((t & 31) == 0) w[t >> 5] = s;
    __syncthreads();
    if (t == 0) g_x2[b * NPTS + i] = w[0] + w[1] + w[2] + w[3];
}

// ---------------- centers0 = X[:KC]; c2 = rowsq(centers) ----------------
__global__ void init_centers_kernel(const float* __restrict__ X) {
    int b = blockIdx.y, k = blockIdx.x, t = threadIdx.x;  // 128 threads
    const float* row = X + ((size_t)b * NPTS + k) * DIM;
    float* crow = g_centers + ((size_t)b * KC + k) * DIM;
    float s = 0.f;
#pragma unroll
    for (int u = 0; u < 4; u++) {
        float v = row[t + 128 * u];
        crow[t + 128 * u] = v;
        s += v * v;
    }
    for (int o = 16; o > 0; o >>= 1) s += __shfl_down_sync(0xffffffffu, s, o);
    __shared__ float w[4];
    if ((t & 31) == 0) w[t >> 5] = s;
    __syncthreads();
    if (t == 0) g_c2[b * KC + k] = w[0] + w[1] + w[2] + w[3];
}

__global__ void reset_best_kernel() {
    int i = blockIdx.x * blockDim.x + threadIdx.x;
    if (i < BATCH * NPTS) g_best[i] = 0xFFFFFFFFFFFFFFFFull;
}

// ============================================================================
// f32x2 GEMM core v2: 128x128 tile, BK=8, 128 threads, 16x8 micro-tile.
// A pairs come packed along M straight from smem (no duplication); B broadcast
// pairs built with register MOVs. FMA-pipe bound by design.
// MODE 0: assign (B = centers, row-major K-inner; epilogue = keyed argmin)
// MODE 1: C = A@B (B is KxN) plain store
// MODE 2: pooled mish epilogue (bias + mish + column sum into g_pooled)
// ============================================================================
template <int MODE>
__global__ __launch_bounds__(128, 2) void gemm_kernel(
    const float* __restrict__ A, const float* __restrict__ B,
    float* __restrict__ C, const float* __restrict__ bias,
    int Kd, int Nn, size_t aBatch, size_t bBatch, size_t cBatch) {
    __shared__ __align__(16) float As[2][8][128];
    __shared__ __align__(16) float Bs[2][8][128];
    __shared__ unsigned long long skey[128];
    __shared__ float colsum[128];

    int b = blockIdx.z;
    const float* Ab = A + (size_t)b * aBatch;
    const float* Bb = B + (size_t)b * bBatch;
    int m0 = blockIdx.x * 128, n0 = blockIdx.y * 128;
    int tid = threadIdx.x;
    int tx = tid & 15, ty = tid >> 4;  // tx: 16 n-groups of 8, ty: 8 m-groups of 16

    // A (and transposed-B) global mapping: thread pair per row, 4 k each
    int ar = tid >> 1, akq = (tid & 1) * 4;
    // natural B (KxN) mapping
    int bkr = tid >> 5, bc4 = (tid & 31) * 4;

    float4 ra0, ra1, rb0, rb1;

    auto loadT = [&](int k0) {
        ra0 = *(const float4*)(Ab + (size_t)(m0 + ar) * Kd + k0 + akq);
        ra1 = *(const float4*)(Ab + (size_t)(m0 + ar + 64) * Kd + k0 + akq);
        if (MODE == 0) {
            rb0 = *(const float4*)(Bb + (size_t)(n0 + ar) * Kd + k0 + akq);
            rb1 = *(const float4*)(Bb + (size_t)(n0 + ar + 64) * Kd + k0 + akq);
        } else {
            rb0 = *(const float4*)(Bb + (size_t)(k0 + bkr) * Nn + n0 + bc4);
            rb1 = *(const float4*)(Bb + (size_t)(k0 + bkr + 4) * Nn + n0 + bc4);
        }
    };
    auto storeT = [&](int s) {
#pragma unroll
        for (int j = 0; j < 4; j++) {
            As[s][akq + j][ar] = (&ra0.x)[j];
            As[s][akq + j][ar + 64] = (&ra1.x)[j];
        }
        if (MODE == 0) {
#pragma unroll
            for (int j = 0; j < 4; j++) {
                Bs[s][akq + j][ar] = (&rb0.x)[j];
                Bs[s][akq + j][ar + 64] = (&rb1.x)[j];
            }
        } else {
            *(float4*)&Bs[s][bkr][bc4] = rb0;
            *(float4*)&Bs[s][bkr + 4][bc4] = rb1;
        }
    };

    // acc[mp][j]: packed pair = rows (ty*16+2mp, ty*16+2mp+1), col tx*8+j
    unsigned long long acc[8][8];
#pragma unroll
    for (int i = 0; i < 8; i++)
#pragma unroll
        for (int j = 0; j < 8; j++) acc[i][j] = 0ull;

    loadT(0);
    storeT(0);
    __syncthreads();

    int nk = Kd >> 3;
    int s = 0;
    for (int t = 0; t < nk; t++) {
        if (t + 1 < nk) loadT((t + 1) << 3);
#pragma unroll
        for (int kk = 0; kk < 8; kk++) {
            const ulonglong2* apv = (const ulonglong2*)&As[s][kk][ty * 16];
            ulonglong2 A0 = apv[0], A1 = apv[1], A2 = apv[2], A3 = apv[3];
            uint4 b0 = *(const uint4*)&Bs[s][kk][tx * 8];
            uint4 b1 = *(const uint4*)&Bs[s][kk][tx * 8 + 4];
            unsigned long long ap[8] = {A0.x, A0.y, A1.x, A1.y,
                                        A2.x, A2.y, A3.x, A3.y};
            unsigned long long bd[8] = {dup2(b0.x), dup2(b0.y), dup2(b0.z),
                                        dup2(b0.w), dup2(b1.x), dup2(b1.y),
                                        dup2(b1.z), dup2(b1.w)};
#pragma unroll
            for (int i = 0; i < 8; i++)
#pragma unroll
                for (int j = 0; j < 8; j++) ffma2(acc[i][j], ap[i], bd[j]);
        }
        if (t + 1 < nk) {
            storeT(s ^ 1);
            __syncthreads();
            s ^= 1;
        }
    }

    if (MODE == 0) {
        skey[tid] = 0xFFFFFFFFFFFFFFFFull;
        float c2v[8];
#pragma unroll
        for (int j = 0; j < 8; j++) c2v[j] = g_c2[b * KC + n0 + tx * 8 + j];
        float x2v[16];
#pragma unroll
        for (int i = 0; i < 16; i++) x2v[i] = g_x2[b * NPTS + m0 + ty * 16 + i];
        __syncthreads();
#pragma unroll
        for (int mp = 0; mp < 8; mp++) {
#pragma unroll
            for (int h = 0; h < 2; h++) {
                int rl = ty * 16 + 2 * mp + h;
                unsigned long long best = 0xFFFFFFFFFFFFFFFFull;
#pragma unroll
                for (int j = 0; j < 8; j++) {
                    float dot = ((const float*)&acc[mp][j])[h];
                    float d = (x2v[2 * mp + h] + c2v[j]) - 2.0f * dot;
                    unsigned u = __float_as_uint(d);
                    u = (u & 0x80000000u) ? ~u : (u | 0x80000000u);
                    unsigned long long key =
                        ((unsigned long long)u << 32) | (unsigned)(n0 + tx * 8 + j);
                    best = (key < best) ? key : best;
                }
                atomicMin(&skey[rl], best);
            }
        }
        __syncthreads();
        atomicMin(&g_best[b * NPTS + m0 + tid], skey[tid]);
    } else if (MODE == 1) {
        float* Cb = C + (size_t)b * cBatch;
#pragma unroll
        for (int mp = 0; mp < 8; mp++) {
#pragma unroll
            for (int h = 0; h < 2; h++) {
                float* p = Cb + (size_t)(m0 + ty * 16 + 2 * mp + h) * Nn + n0 + tx * 8;
                float4 v0, v1;
#pragma unroll
                for (int j = 0; j < 4; j++) {
                    (&v0.x)[j] = ((const float*)&acc[mp][j])[h];
                    (&v1.x)[j] = ((const float*)&acc[mp][j + 4])[h];
                }
                *(float4*)p = v0;
                *(float4*)(p + 4) = v1;
            }
        }
    } else {
        colsum[tid] = 0.f;
        float bj[8];
#pragma unroll
        for (int j = 0; j < 8; j++) bj[j] = bias[n0 + tx * 8 + j];
        __syncthreads();
        float part[8] = {0, 0, 0, 0, 0, 0, 0, 0};
#pragma unroll
        for (int mp = 0; mp < 8; mp++)
#pragma unroll
            for (int j = 0; j < 8; j++) {
                part[j] += mishf(((const float*)&acc[mp][j])[0] + bj[j]);
                part[j] += mishf(((const float*)&acc[mp][j])[1] + bj[j]);
            }
#pragma unroll
        for (int j = 0; j < 8; j++) atomicAdd(&colsum[tx * 8 + j], part[j]);
        __syncthreads();
        atomicAdd(&g_pooled[b * DIM + n0 + tid], colsum[tid]);
    }
}

// ---------------- deterministic cluster member-list build ----------------
__global__ __launch_bounds__(256) void listbuild_kernel() {
    __shared__ int cnts[KC];
    __shared__ int offs[KC];
    __shared__ int cur[KC];
    __shared__ int labs[NPTS];
    int b = blockIdx.x, t = threadIdx.x;
    for (int k = t; k < KC; k += 256) cnts[k] = 0;
    __syncthreads();
    for (int i = t; i < NPTS; i += 256) {
        int l = (int)(g_best[b * NPTS + i] & 0xFFFFFFFFu);
        labs[i] = l;
        g_labels[b * NPTS + i] = l;
        atomicAdd(&cnts[l], 1);
    }
    __syncthreads();
    if (t < 32) {
        int carry = 0;
        for (int c = 0; c < KC / 32; c++) {
            int v = cnts[c * 32 + t];
            int x = v;
#pragma unroll
            for (int o = 1; o < 32; o <<= 1) {
                int y = __shfl_up_sync(0xffffffffu, x, o);
                if (t >= o) x += y;
            }
            offs[c * 32 + t] = carry + x - v;
            carry += __shfl_sync(0xffffffffu, x, 31);
        }
    }
    __syncthreads();
    for (int k = t; k < KC; k += 256) {
        cur[k] = offs[k];
        g_counts[b * KC + k] = cnts[k];
        g_offs[b * KC + k] = offs[k];
    }
    __syncthreads();
    if (t < 32) {
        unsigned below = (t == 0) ? 0u : (0xffffffffu >> (32 - t));
        for (int c = 0; c < NPTS / 32; c++) {
            int i = c * 32 + t;
            int l = labs[i];
            unsigned mask = __match_any_sync(0xffffffffu, l);
            int base = cur[l];
            __syncwarp();
            int rank = __popc(mask & below);
            g_list[b * NPTS + base + rank] = i;
            if (t == __ffs(mask) - 1) cur[l] = base + __popc(mask);
            __syncwarp();
        }
    }
}

// ---------------- center update: gather listed members (ascending order) ----
__global__ void gather_update_kernel(const float* __restrict__ X) {
    int b = blockIdx.y, k = blockIdx.x, t = threadIdx.x;  // 128 threads
    int cnt = g_counts[b * KC + k];
    int off = g_offs[b * KC + k];
    const int* lst = g_list + b * NPTS + off;
    const float* Xb = X + (size_t)b * NPTS * DIM;
    float a0 = 0, a1 = 0, a2 = 0, a3 = 0;
    for (int e = 0; e < cnt; e++) {
        const float* xr = Xb + (size_t)lst[e] * DIM;
        a0 += xr[t]; a1 += xr[t + 128]; a2 += xr[t + 256]; a3 += xr[t + 384];
    }
    float* crow = g_centers + ((size_t)b * KC + k) * DIM;
    float v0, v1, v2, v3;
    if (cnt > 0) {
        float cf = (float)cnt;
        v0 = a0 / cf; v1 = a1 / cf; v2 = a2 / cf; v3 = a3 / cf;
        crow[t] = v0; crow[t + 128] = v1; crow[t + 256] = v2; crow[t + 384] = v3;
    } else {
        v0 = crow[t]; v1 = crow[t + 128]; v2 = crow[t + 256]; v3 = crow[t + 384];
    }
    float sq = v0 * v0 + v1 * v1 + v2 * v2 + v3 * v3;
    for (int o = 16; o > 0; o >>= 1) sq += __shfl_down_sync(0xffffffffu, sq, o);
    __shared__ float w[4];
    if ((t & 31) == 0) w[t >> 5] = sq;
    __syncthreads();
    if (t == 0) g_c2[b * KC + k] = w[0] + w[1] + w[2] + w[3];
}

// ---------------- h_next = mish(adj @ one_hot(labels)), 8 rows/block --------
__global__ __launch_bounds__(256) void segsum_mish_kernel(const float* __restrict__ adj,
                                                          float* __restrict__ Hout) {
    int b = blockIdx.y, i0 = blockIdx.x * 8, t = threadIdx.x;  // 256 threads
    __shared__ float acc[8][KC];
    __shared__ int labs[NPTS];
    const int* lb = g_labels + b * NPTS;
    for (int j = t; j < NPTS; j += 256) labs[j] = lb[j];
#pragma unroll
    for (int r = 0; r < 8; r++)
        for (int k = t; k < KC; k += 256) acc[r][k] = 0.f;
    __syncthreads();
#pragma unroll
    for (int r = 0; r < 8; r++) {
        const float* arow = adj + ((size_t)b * NPTS + i0 + r) * NPTS;
        for (int j = t; j < NPTS; j += 256) atomicAdd(&acc[r][labs[j]], arow[j]);
    }
    __syncthreads();
#pragma unroll
    for (int r = 0; r < 8; r++) {
        float* hrow = Hout + ((size_t)b * NPTS + i0 + r) * DIM;
        for (int k = t; k < KC; k += 256) hrow[k] = mishf(acc[r][k]);
    }
}

__global__ void zero_pooled_kernel() {
    g_pooled[blockIdx.x * DIM + threadIdx.x] = 0.f;
}

// ---------------- out = pooled @ Wp + bp ----------------
__global__ void out_kernel(const float* __restrict__ Wp, const float* __restrict__ bp,
                           float* __restrict__ out) {
    int b = blockIdx.x, t = threadIdx.x;  // 32 threads
    if (t < OUTD) {
        const float* p = g_pooled + b * DIM;
        float s = 0.f;
        for (int h = 0; h < DIM; h++) s += p[h] * Wp[h * OUTD + t];
        out[b * OUTD + t] = s + bp[t];
    }
}

// ---------------- host orchestration ----------------
static void run_ctod(const float* X, const float* centers) {
    rowsq_kernel<<<dim3(NPTS, BATCH), 128>>>(X);
    init_centers_kernel<<<dim3(KC, BATCH), 128>>>(X);
    for (int it = 0; it < 10; it++) {
        reset_best_kernel<<<(BATCH * NPTS) / 256, 256>>>();
        gemm_kernel<0><<<dim3(NPTS / 128, KC / 128, BATCH), 128>>>(
            X, centers, nullptr, nullptr, DIM, KC,
            (size_t)NPTS * DIM, (size_t)KC * DIM, (size_t)0);
        listbuild_kernel<<<BATCH, 256>>>();
        if (it < 9) gather_update_kernel<<<dim3(KC, BATCH), 128>>>(X);
    }
}

extern "C" void kernel_launch(void* const* d_in, const int* in_sizes, int n_in,
                              void* d_out, int out_size) {
    const float* x   = (const float*)d_in[0];
    const float* adj = (const float*)d_in[1];
    const float* W   = (const float*)d_in[2];
    const float* bb  = (const float*)d_in[3];
    const float* Wp  = (const float*)d_in[4];
    const float* bp  = (const float*)d_in[5];
    float* out = (float*)d_out;

    float *h0, *h1, *centers;
    cudaGetSymbolAddress((void**)&h0, g_buf0);
    cudaGetSymbolAddress((void**)&h1, g_buf1);
    cudaGetSymbolAddress((void**)&centers, g_centers);

    // Layer 1
    run_ctod(x, centers);
    segsum_mish_kernel<<<dim3(NPTS / 8, BATCH), 256>>>(adj, h0);
    // Layer 2
    run_ctod(h0, centers);
    segsum_mish_kernel<<<dim3(NPTS / 8, BATCH), 256>>>(adj, h1);
    // Layer 3
    run_ctod(h1, centers);
    segsum_mish_kernel<<<dim3(NPTS / 8, BATCH), 256>>>(adj, h0);

    // Final layer: t = h0 @ W, then pooled mish(adj @ t + b)
    gemm_kernel<1><<<dim3(NPTS / 128, DIM / 128, BATCH), 128>>>(
        h0, W, h1, nullptr, DIM, DIM,
        (size_t)NPTS * DIM, (size_t)0, (size_t)NPTS * DIM);
    zero_pooled_kernel<<<BATCH, DIM>>>();
    gemm_kernel<2><<<dim3(NPTS / 128, DIM / 128, BATCH), 128>>>(
        adj, h1, nullptr, bb, NPTS, DIM,
        (size_t)NPTS * NPTS, (size_t)NPTS * DIM, (size_t)0);
    out_kernel<<<BATCH, 32>>>(Wp, bp, out);
}